// round 3
// baseline (speedup 1.0000x reference)
#include <cuda_runtime.h>
#include <cstdint>
#include <cstddef>

// ============================================================================
// Llama4 MoE Router on sm_103:
//   logits[32768,64] = hs[32768,4096] @ gate_w[64,4096]^T
//   weights = renormalized top-2 softmax; indices = top-2 experts.
// mma.sync.m16n8k8.tf32 + ldmatrix + cp.async 4-stage pipe.
// Near-tie tokens (gap < EPS) get exact double-precision re-ranking.
// Output (float32): [weights 32768*2][indices 32768*2][logits 32768*64]
// ============================================================================

#define TOKENS   32768
#define KDIM     4096
#define NEXP     64
#define BM       128
#define BK       32
#define NSTAGES  4
#define KITERS   (KDIM / BK)            // 128
#define THREADS  256
#define EPS      6e-3f

#define A_BYTES     (BM * BK * 4)       // 16384
#define B_BYTES     (NEXP * BK * 4)     // 8192
#define STAGE_BYTES (A_BYTES + B_BYTES) // 24576
#define SMEM_TOTAL  (NSTAGES * STAGE_BYTES)  // 98304
#define LG_STRIDE   68                  // padded logits row (floats)

__device__ __forceinline__ uint32_t smem_u32(const void* p) {
    uint32_t a;
    asm("{ .reg .u64 t; cvta.to.shared.u64 t, %1; cvt.u32.u64 %0, t; }" : "=r"(a) : "l"(p));
    return a;
}

__device__ __forceinline__ void cp16(uint32_t s, const void* g) {
    asm volatile("cp.async.cg.shared.global [%0], [%1], 16;" :: "r"(s), "l"(g) : "memory");
}

__device__ __forceinline__ void ldsm4(uint32_t& r0, uint32_t& r1, uint32_t& r2, uint32_t& r3,
                                      uint32_t addr) {
    asm volatile("ldmatrix.sync.aligned.m8n8.x4.shared.b16 {%0,%1,%2,%3}, [%4];"
                 : "=r"(r0), "=r"(r1), "=r"(r2), "=r"(r3) : "r"(addr));
}

__device__ __forceinline__ uint32_t rna_tf32(uint32_t x) {
    uint32_t r;
    asm("cvt.rna.tf32.f32 %0, %1;" : "=r"(r) : "f"(__uint_as_float(x)));
    return r;
}

__device__ __forceinline__ void mma8(float c[4], const uint32_t a[4], uint32_t b0, uint32_t b1) {
    asm volatile(
        "mma.sync.aligned.m16n8k8.row.col.f32.tf32.tf32.f32 "
        "{%0,%1,%2,%3}, {%4,%5,%6,%7}, {%8,%9}, {%0,%1,%2,%3};"
        : "+f"(c[0]), "+f"(c[1]), "+f"(c[2]), "+f"(c[3])
        : "r"(a[0]), "r"(a[1]), "r"(a[2]), "r"(a[3]), "r"(b0), "r"(b1));
}

// One K-chunk: A[128,32] + B[64,32] fp32 into stage s, 16B-chunk XOR swizzle.
__device__ __forceinline__ void load_stage(const float* __restrict__ hs,
                                           const float* __restrict__ gw,
                                           int m0, int kc, uint32_t sbase, int s, int tid) {
    const uint32_t ab = sbase + s * STAGE_BYTES;
    const uint32_t bb = ab + A_BYTES;
    #pragma unroll
    for (int j = 0; j < 4; j++) {                 // A: 1024 chunks / 256 thr
        int c  = tid + j * 256;
        int r  = c >> 3;
        int ch = c & 7;
        cp16(ab + r * 128 + ((ch ^ (r & 7)) << 4),
             hs + (size_t)(m0 + r) * KDIM + kc + ch * 4);
    }
    #pragma unroll
    for (int j = 0; j < 2; j++) {                 // B: 512 chunks / 256 thr
        int c  = tid + j * 256;
        int e  = c >> 3;
        int ch = c & 7;
        cp16(bb + e * 128 + ((ch ^ (e & 7)) << 4),
             gw + (size_t)e * KDIM + kc + ch * 4);
    }
}

__global__ __launch_bounds__(THREADS, 2)
void router_kernel(const float* __restrict__ hs, const float* __restrict__ gw,
                   float* __restrict__ out) {
    extern __shared__ char smem[];
    const uint32_t sb = smem_u32(smem);
    const int tid  = threadIdx.x;
    const int wid  = tid >> 5;
    const int lane = tid & 31;
    const int m0   = blockIdx.x * BM;
    const int wm   = wid >> 1;            // 0..3 (M)
    const int wn   = wid & 1;             // 0..1 (N)
    const int lmat = lane >> 3;           // ldmatrix quadrant 0..3
    const int l8   = lane & 7;

    float c[2][4][4];
    #pragma unroll
    for (int mt = 0; mt < 2; mt++)
        #pragma unroll
        for (int nt = 0; nt < 4; nt++)
            #pragma unroll
            for (int q = 0; q < 4; q++) c[mt][nt][q] = 0.0f;

    #pragma unroll
    for (int j = 0; j < NSTAGES - 1; j++) {
        load_stage(hs, gw, m0, j * BK, sb, j, tid);
        asm volatile("cp.async.commit_group;" ::: "memory");
    }

    for (int i = 0; i < KITERS; i++) {
        asm volatile("cp.async.wait_group %0;" :: "n"(NSTAGES - 2) : "memory");
        __syncthreads();

        const uint32_t ab = sb + (i % NSTAGES) * STAGE_BYTES;
        const uint32_t bb = ab + A_BYTES;

        #pragma unroll
        for (int ks = 0; ks < 4; ks++) {          // 4 x K=8
            const int ck = ks * 2;

            uint32_t a[2][4];
            #pragma unroll
            for (int mt = 0; mt < 2; mt++) {
                int r  = wm * 32 + mt * 16 + l8 + ((lmat & 1) << 3);
                int cc = ck + (lmat >> 1);
                ldsm4(a[mt][0], a[mt][1], a[mt][2], a[mt][3],
                      ab + r * 128 + ((cc ^ (r & 7)) << 4));
            }
            uint32_t b[2][4];
            #pragma unroll
            for (int p = 0; p < 2; p++) {
                int r  = wn * 32 + p * 16 + l8 + ((lmat >> 1) << 3);
                int cc = ck + (lmat & 1);
                ldsm4(b[p][0], b[p][1], b[p][2], b[p][3],
                      bb + r * 128 + ((cc ^ (r & 7)) << 4));
            }
            #pragma unroll
            for (int mt = 0; mt < 2; mt++)
                #pragma unroll
                for (int q = 0; q < 4; q++) a[mt][q] = rna_tf32(a[mt][q]);
            #pragma unroll
            for (int p = 0; p < 2; p++)
                #pragma unroll
                for (int q = 0; q < 4; q++) b[p][q] = rna_tf32(b[p][q]);

            #pragma unroll
            for (int mt = 0; mt < 2; mt++)
                #pragma unroll
                for (int nt = 0; nt < 4; nt++)
                    mma8(c[mt][nt], a[mt], b[nt >> 1][(nt & 1) * 2],
                                           b[nt >> 1][(nt & 1) * 2 + 1]);
        }

        const int kn = i + NSTAGES - 1;
        if (kn < KITERS) load_stage(hs, gw, m0, kn * BK, sb, kn % NSTAGES, tid);
        asm volatile("cp.async.commit_group;" ::: "memory");
    }

    asm volatile("cp.async.wait_group 0;" ::: "memory");
    __syncthreads();

    // ---- Epilogue ----------------------------------------------------------
    float* lgs     = reinterpret_cast<float*>(smem);             // [128][68]
    float* sthresh = reinterpret_cast<float*>(smem + BM * LG_STRIDE * 4);
    int*   slist   = reinterpret_cast<int*>(sthresh + BM);
    int*   scount  = slist + BM;
    if (tid == 0) *scount = 0;

    const int g = lane >> 2, q = lane & 3;
    float* lg_out = out + 4 * TOKENS;
    #pragma unroll
    for (int mt = 0; mt < 2; mt++) {
        const int r0 = wm * 32 + mt * 16 + g;
        #pragma unroll
        for (int nt = 0; nt < 4; nt++) {
            const int col = wn * 32 + nt * 8 + 2 * q;
            lgs[r0 * LG_STRIDE + col]           = c[mt][nt][0];
            lgs[r0 * LG_STRIDE + col + 1]       = c[mt][nt][1];
            lgs[(r0 + 8) * LG_STRIDE + col]     = c[mt][nt][2];
            lgs[(r0 + 8) * LG_STRIDE + col + 1] = c[mt][nt][3];
            *reinterpret_cast<float2*>(lg_out + (size_t)(m0 + r0) * NEXP + col) =
                make_float2(c[mt][nt][0], c[mt][nt][1]);
            *reinterpret_cast<float2*>(lg_out + (size_t)(m0 + r0 + 8) * NEXP + col) =
                make_float2(c[mt][nt][2], c[mt][nt][3]);
        }
    }
    __syncthreads();

    if (tid < BM) {
        const int t = m0 + tid;
        float m1 = -1e30f, m2 = -1e30f, m3 = -1e30f;
        int i1 = 0, i2 = 0;
        #pragma unroll
        for (int j = 0; j < 16; j++) {
            float4 v = *reinterpret_cast<float4*>(&lgs[tid * LG_STRIDE + 4 * j]);
            float vv[4] = {v.x, v.y, v.z, v.w};
            #pragma unroll
            for (int u = 0; u < 4; u++) {
                int idx = 4 * j + u;
                if (vv[u] > m1)      { m3 = m2; m2 = m1; i2 = i1; m1 = vv[u]; i1 = idx; }
                else if (vv[u] > m2) { m3 = m2; m2 = vv[u]; i2 = idx; }
                else if (vv[u] > m3) { m3 = vv[u]; }
            }
        }
        if ((m1 - m2 < EPS) || (m2 - m3 < EPS)) {
            sthresh[tid] = m2 - EPS;
            slist[atomicAdd(scount, 1)] = tid;
        } else {
            const float e   = __expf(m2 - m1);
            const float inv = 1.0f / (1.0f + e);
            *reinterpret_cast<float2*>(out + 2 * t) = make_float2(inv, e * inv);
            *reinterpret_cast<float2*>(out + 2 * TOKENS + 2 * t) =
                make_float2((float)i1, (float)i2);
        }
    }
    __syncthreads();

    // Exact re-ranking of flagged tokens: one warp per token, double accumulation.
    const int nflag = *scount;
    for (int fi = wid; fi < nflag; fi += THREADS / 32) {
        const int row = slist[fi];
        const int t   = m0 + row;
        const float thr = sthresh[row];
        double b1 = -1e300, b2 = -1e300;
        int j1 = 0, j2 = 0;
        const float4* ha = reinterpret_cast<const float4*>(hs + (size_t)t * KDIM);
        for (int e = 0; e < NEXP; e++) {
            if (lgs[row * LG_STRIDE + e] < thr) continue;
            const float4* ga = reinterpret_cast<const float4*>(gw + (size_t)e * KDIM);
            double acc = 0.0;
            #pragma unroll 4
            for (int k = lane; k < KDIM / 4; k += 32) {
                float4 x = ha[k];
                float4 y = ga[k];
                acc += (double)x.x * y.x + (double)x.y * y.y
                     + (double)x.z * y.z + (double)x.w * y.w;
            }
            #pragma unroll
            for (int o = 16; o; o >>= 1) acc += __shfl_down_sync(0xffffffffu, acc, o);
            acc = __shfl_sync(0xffffffffu, acc, 0);
            if (acc > b1)      { b2 = b1; j2 = j1; b1 = acc; j1 = e; }
            else if (acc > b2) { b2 = acc; j2 = e; }
        }
        if (lane == 0) {
            const float e   = __expf((float)(b2 - b1));
            const float inv = 1.0f / (1.0f + e);
            *reinterpret_cast<float2*>(out + 2 * t) = make_float2(inv, e * inv);
            *reinterpret_cast<float2*>(out + 2 * TOKENS + 2 * t) =
                make_float2((float)j1, (float)j2);
        }
    }
}

extern "C" void kernel_launch(void* const* d_in, const int* in_sizes, int n_in,
                              void* d_out, int out_size) {
    (void)in_sizes; (void)n_in; (void)out_size;
    const float* hs = (const float*)d_in[0];   // [32768, 4096]
    const float* gw = (const float*)d_in[1];   // [64, 4096]
    float* out = (float*)d_out;

    cudaFuncSetAttribute(router_kernel,
                         cudaFuncAttributeMaxDynamicSharedMemorySize, SMEM_TOTAL);
    router_kernel<<<TOKENS / BM, THREADS, SMEM_TOTAL>>>(hs, gw, out);
}